// round 14
// baseline (speedup 1.0000x reference)
#include <cuda_runtime.h>
#include <cuda_fp16.h>

#define NN 100000
#define NE 1600000
#define SCAN_NT 256
#define SCAN_ITEMS 1024
#define SCAN_NB ((NN + SCAN_ITEMS - 1) / SCAN_ITEMS)   // 98

// ---------------- scratch (device globals; no allocation) ----------------
__device__ __align__(16) __half g_hh[(size_t)NN * 128];  // projected features (fp16, gather-only)
__device__ __align__(16) float g_asrc[NN * 4];           // per-node src att logits
__device__ __align__(16) float g_adst[NN * 4];           // per-node dst att logits
__device__ int g_bin[NE];                  // src indices grouped by dst (CSR)
__device__ int g_cnt[NN];
__device__ int g_ofs[NN];
__device__ int g_cur[NN];
__device__ int g_part[SCAN_NB];
__device__ int g_pofs[SCAN_NB];
__device__ int g_is64;
__device__ float g_sum[128];
__device__ float g_sq[128];
__device__ __align__(16) float g_scale[128];
__device__ __align__(16) float g_shift[128];

__device__ __forceinline__ float lrelu(float v) { return v > 0.f ? v : 0.2f * v; }
__device__ __forceinline__ unsigned f2tf32(float f) {
    unsigned u;
    asm("cvt.rna.tf32.f32 %0, %1;" : "=r"(u) : "f"(f));
    return u;
}
__device__ __forceinline__ void mma_tf32(float c[4], unsigned a0, unsigned a1,
                                         unsigned a2, unsigned a3,
                                         unsigned b0, unsigned b1) {
    asm volatile(
        "mma.sync.aligned.m16n8k8.row.col.f32.tf32.tf32.f32 "
        "{%0,%1,%2,%3}, {%4,%5,%6,%7}, {%8,%9}, {%0,%1,%2,%3};"
        : "+f"(c[0]), "+f"(c[1]), "+f"(c[2]), "+f"(c[3])
        : "r"(a0), "r"(a1), "r"(a2), "r"(a3), "r"(b0), "r"(b1));
}
__device__ __forceinline__ int clampN(long long v) {
    if (v < 0) v = 0;
    if (v > NN - 1) v = NN - 1;
    return (int)v;
}

struct __align__(8) h2x2 { __half2 a, b; };

// ---------------- K-zero ----------------
__global__ void k_zero() {
    int t = blockIdx.x * blockDim.x + threadIdx.x;
    if (t < NN) g_cnt[t] = 0;
    if (t < 128) { g_sum[t] = 0.f; g_sq[t] = 0.f; }
}

// ---------------- K-detect: int64 vs int32 edge_index (parallel ballot) ----------------
__global__ void k_detect(const unsigned long long* __restrict__ e) {
    int lane = threadIdx.x;
    bool good = (e[lane] < (unsigned long long)NN) &&
                (e[32 + lane] < (unsigned long long)NN);
    unsigned b = __ballot_sync(0xffffffffu, good);
    if (lane == 0) g_is64 = (b == 0xffffffffu) ? 1 : 0;
}

// ---------------- K-convert: per-dst histogram, 4 edges/thread vectorized ----------------
__global__ void k_convert(const void* __restrict__ ep) {
    int i4 = blockIdx.x * blockDim.x + threadIdx.x;   // group of 4 edges
    int base = i4 * 4;
    if (base >= NE) return;
    int d[4];
    if (g_is64) {
        const longlong2* e2 = (const longlong2*)((const long long*)ep + NE);
        longlong2 a = e2[i4 * 2];
        longlong2 b = e2[i4 * 2 + 1];
        d[0] = clampN(a.x); d[1] = clampN(a.y); d[2] = clampN(b.x); d[3] = clampN(b.y);
    } else {
        const int4* e4 = (const int4*)((const int*)ep + NE);
        int4 a = e4[i4];
        d[0] = clampN(a.x); d[1] = clampN(a.y); d[2] = clampN(a.z); d[3] = clampN(a.w);
    }
#pragma unroll
    for (int j = 0; j < 4; j++)
        if (base + j < NE) atomicAdd(&g_cnt[d[j]], 1);
}

// ---------------- 3-kernel exclusive scan of g_cnt -> g_ofs (R8 structure) ----------------
__global__ void k_psum() {
    __shared__ int sm[SCAN_NT];
    int b = blockIdx.x, t = threadIdx.x;
    int base = b * SCAN_ITEMS + t * 4;
    int s = 0;
#pragma unroll
    for (int j = 0; j < 4; j++) { int i = base + j; if (i < NN) s += g_cnt[i]; }
    sm[t] = s; __syncthreads();
    for (int off = SCAN_NT / 2; off > 0; off >>= 1) {
        if (t < off) sm[t] += sm[t + off];
        __syncthreads();
    }
    if (t == 0) g_part[b] = sm[0];
}

__global__ void k_scanp() {
    __shared__ int sm[128];
    int t = threadIdx.x;
    int v = (t < SCAN_NB) ? g_part[t] : 0;
    sm[t] = v; __syncthreads();
    for (int off = 1; off < 128; off <<= 1) {
        int a = (t >= off) ? sm[t - off] : 0;
        __syncthreads(); sm[t] += a; __syncthreads();
    }
    if (t < SCAN_NB) g_pofs[t] = sm[t] - v;
}

__global__ void k_base() {
    __shared__ int sm[SCAN_NT];
    int b = blockIdx.x, t = threadIdx.x;
    int base = b * SCAN_ITEMS + t * 4;
    int c[4]; int s = 0;
#pragma unroll
    for (int j = 0; j < 4; j++) {
        int i = base + j;
        c[j] = (i < NN) ? g_cnt[i] : 0;
        s += c[j];
    }
    sm[t] = s; __syncthreads();
    for (int off = 1; off < SCAN_NT; off <<= 1) {
        int a = (t >= off) ? sm[t - off] : 0;
        __syncthreads(); sm[t] += a; __syncthreads();
    }
    int ex = sm[t] - s + g_pofs[b];
#pragma unroll
    for (int j = 0; j < 4; j++) {
        int i = base + j;
        if (i < NN) { g_ofs[i] = ex; g_cur[i] = ex; }
        ex += c[j];
    }
}

// ---------------- K-scatter: CSR fill, 4 edges/thread vectorized ----------------
__global__ void k_scatter(const void* __restrict__ ep) {
    int i4 = blockIdx.x * blockDim.x + threadIdx.x;
    int base = i4 * 4;
    if (base >= NE) return;
    int s[4], d[4];
    if (g_is64) {
        const longlong2* es = (const longlong2*)((const long long*)ep);
        const longlong2* ed = (const longlong2*)((const long long*)ep + NE);
        longlong2 sa = es[i4 * 2], sb = es[i4 * 2 + 1];
        longlong2 da = ed[i4 * 2], db = ed[i4 * 2 + 1];
        s[0] = clampN(sa.x); s[1] = clampN(sa.y); s[2] = clampN(sb.x); s[3] = clampN(sb.y);
        d[0] = clampN(da.x); d[1] = clampN(da.y); d[2] = clampN(db.x); d[3] = clampN(db.y);
    } else {
        const int4* es = (const int4*)((const int*)ep);
        const int4* ed = (const int4*)((const int*)ep + NE);
        int4 sa = es[i4], da = ed[i4];
        s[0] = clampN(sa.x); s[1] = clampN(sa.y); s[2] = clampN(sa.z); s[3] = clampN(sa.w);
        d[0] = clampN(da.x); d[1] = clampN(da.y); d[2] = clampN(da.z); d[3] = clampN(da.w);
    }
#pragma unroll
    for (int j = 0; j < 4; j++) {
        if (base + j < NE) {
            int pos = atomicAdd(&g_cur[d[j]], 1);
            g_bin[pos] = s[j];
        }
    }
}

// ---------------- K1: h = x @ W via tf32 mma.sync + fused att logits ----------------
__global__ __launch_bounds__(256) void k_gemm_att(const float* __restrict__ x,
                                                  const float* __restrict__ W,
                                                  const float* __restrict__ att_src,
                                                  const float* __restrict__ att_dst) {
    __shared__ unsigned xs[128][36];   // x chunk [row][k], tf32
    __shared__ unsigned Wsh[32][136];  // W chunk [k][n], tf32
    __shared__ float attb[256];        // [0:128) att_src, [128:256) att_dst
    int t = threadIdx.x;
    int w = t >> 5, lane = t & 31;
    int r0 = w * 16;
    int row0 = blockIdx.x * 128;
    int lg = lane >> 2, lc = lane & 3;
    attb[t] = (t < 128) ? __ldg(&att_src[t]) : __ldg(&att_dst[t - 128]);

    float c[16][4];
#pragma unroll
    for (int nt = 0; nt < 16; nt++)
#pragma unroll
        for (int j = 0; j < 4; j++) c[nt][j] = 0.f;

    const float4* x4 = (const float4*)x;
    const float4* W4 = (const float4*)W;
    for (int ch = 0; ch < 4; ch++) {
#pragma unroll
        for (int j = 0; j < 4; j++) {           // W chunk [32 k][128 n]
            int f = t + 256 * j;
            int k = f >> 5, c4 = f & 31;
            float4 v = W4[(ch * 32 + k) * 32 + c4];
            uint4 u = make_uint4(f2tf32(v.x), f2tf32(v.y), f2tf32(v.z), f2tf32(v.w));
            *(uint4*)&Wsh[k][c4 * 4] = u;
        }
#pragma unroll
        for (int j = 0; j < 4; j++) {           // x chunk [128 rows][32 k]
            int f = t + 256 * j;
            int row = f >> 3, q = f & 7;
            int gr = row0 + row; if (gr > NN - 1) gr = NN - 1;
            float4 v = x4[(size_t)gr * 32 + ch * 8 + q];
            uint4 u = make_uint4(f2tf32(v.x), f2tf32(v.y), f2tf32(v.z), f2tf32(v.w));
            *(uint4*)&xs[row][q * 4] = u;
        }
        __syncthreads();
#pragma unroll
        for (int ks = 0; ks < 4; ks++) {
            int kc = ks * 8;
            unsigned a0 = xs[r0 + lg][kc + lc];
            unsigned a1 = xs[r0 + lg + 8][kc + lc];
            unsigned a2 = xs[r0 + lg][kc + lc + 4];
            unsigned a3 = xs[r0 + lg + 8][kc + lc + 4];
#pragma unroll
            for (int nt = 0; nt < 16; nt++) {
                unsigned b0 = Wsh[kc + lc][nt * 8 + lg];
                unsigned b1 = Wsh[kc + lc + 4][nt * 8 + lg];
                mma_tf32(c[nt], a0, a1, a2, a3, b0, b1);
            }
        }
        __syncthreads();
    }

    // epilogue: fused attention logits + fp16 h store
    float s1[4] = {0,0,0,0}, s2[4] = {0,0,0,0};
    float d1[4] = {0,0,0,0}, d2[4] = {0,0,0,0};
#pragma unroll
    for (int m = 0; m < 4; m++) {
#pragma unroll
        for (int q = 0; q < 4; q++) {
            int nt = m * 4 + q;
            int col = nt * 8 + 2 * lc;
            float as0 = attb[col], as1 = attb[col + 1];
            float ad0 = attb[128 + col], ad1 = attb[128 + col + 1];
            s1[m] += c[nt][0] * as0 + c[nt][1] * as1;
            d1[m] += c[nt][0] * ad0 + c[nt][1] * ad1;
            s2[m] += c[nt][2] * as0 + c[nt][3] * as1;
            d2[m] += c[nt][2] * ad0 + c[nt][3] * ad1;
        }
    }
#pragma unroll
    for (int off = 1; off <= 2; off <<= 1) {
#pragma unroll
        for (int m = 0; m < 4; m++) {
            s1[m] += __shfl_xor_sync(0xffffffffu, s1[m], off);
            s2[m] += __shfl_xor_sync(0xffffffffu, s2[m], off);
            d1[m] += __shfl_xor_sync(0xffffffffu, d1[m], off);
            d2[m] += __shfl_xor_sync(0xffffffffu, d2[m], off);
        }
    }
    int rowA = row0 + r0 + lg;
    int rowB = rowA + 8;
    if (lc == 0) {
        if (rowA < NN) {
            *(float4*)&g_asrc[rowA * 4] = make_float4(s1[0], s1[1], s1[2], s1[3]);
            *(float4*)&g_adst[rowA * 4] = make_float4(d1[0], d1[1], d1[2], d1[3]);
        }
        if (rowB < NN) {
            *(float4*)&g_asrc[rowB * 4] = make_float4(s2[0], s2[1], s2[2], s2[3]);
            *(float4*)&g_adst[rowB * 4] = make_float4(d2[0], d2[1], d2[2], d2[3]);
        }
    }
    __half2* hh2 = (__half2*)g_hh;
    if (rowA < NN) {
#pragma unroll
        for (int nt = 0; nt < 16; nt++)
            hh2[(size_t)rowA * 64 + nt * 4 + lc] =
                __float22half2_rn(make_float2(c[nt][0], c[nt][1]));
    }
    if (rowB < NN) {
#pragma unroll
        for (int nt = 0; nt < 16; nt++)
            hh2[(size_t)rowB * 64 + nt * 4 + lc] =
                __float22half2_rn(make_float2(c[nt][2], c[nt][3]));
    }
}

// ---------------- K3: warp-per-node GAT aggregation, gather unroll x2, occ pinned ----------------
__global__ __launch_bounds__(256, 6) void k_agg(float* __restrict__ out) {
    __shared__ int   ss[8][32];
    __shared__ float ws[8][32 * 4];
    __shared__ float bsum[8][128];
    __shared__ float bsq[8][128];
    int warp = threadIdx.x >> 5, lane = threadIdx.x & 31;
    int n = blockIdx.x * 8 + warp;
    int head = lane >> 3;
    float4 o = make_float4(0.f, 0.f, 0.f, 0.f);

    if (n < NN) {
        int beg = g_ofs[n], cnt = g_cnt[n];
        float4 ad = *(const float4*)&g_adst[n * 4];
        float4 acc = make_float4(0.f, 0.f, 0.f, 0.f);
        float4 den = make_float4(0.f, 0.f, 0.f, 0.f);
        const __half2* hhb = (const __half2*)g_hh;

        for (int c0 = 0; c0 < cnt; c0 += 32) {
            int m = cnt - c0; if (m > 32) m = 32;
            float4 w = make_float4(0.f, 0.f, 0.f, 0.f);
            int s = 0;
            if (lane < m) {
                s = g_bin[beg + c0 + lane];
                float4 a = *(const float4*)&g_asrc[s * 4];
                w.x = __expf(lrelu(a.x + ad.x));
                w.y = __expf(lrelu(a.y + ad.y));
                w.z = __expf(lrelu(a.z + ad.z));
                w.w = __expf(lrelu(a.w + ad.w));
            }
            ss[warp][lane] = s;
            *(float4*)&ws[warp][lane * 4] = w;
            float4 wr = w;
            for (int off = 16; off > 0; off >>= 1) {
                wr.x += __shfl_xor_sync(0xffffffffu, wr.x, off);
                wr.y += __shfl_xor_sync(0xffffffffu, wr.y, off);
                wr.z += __shfl_xor_sync(0xffffffffu, wr.z, off);
                wr.w += __shfl_xor_sync(0xffffffffu, wr.w, off);
            }
            den.x += wr.x; den.y += wr.y; den.z += wr.z; den.w += wr.w;
            __syncwarp();
            // gather unrolled by 2: two independent row loads in flight
            int j = 0;
            for (; j + 2 <= m; j += 2) {
                int s0 = ss[warp][j];
                int s1g = ss[warp][j + 1];
                float w0 = ws[warp][j * 4 + head];
                float w1 = ws[warp][(j + 1) * 4 + head];
                h2x2 h0 = *(const h2x2*)&hhb[(size_t)s0 * 64 + lane * 2];
                h2x2 h1 = *(const h2x2*)&hhb[(size_t)s1g * 64 + lane * 2];
                float2 a0 = __half22float2(h0.a), b0 = __half22float2(h0.b);
                float2 a1 = __half22float2(h1.a), b1 = __half22float2(h1.b);
                acc.x += w0 * a0.x + w1 * a1.x;
                acc.y += w0 * a0.y + w1 * a1.y;
                acc.z += w0 * b0.x + w1 * b1.x;
                acc.w += w0 * b0.y + w1 * b1.y;
            }
            if (j < m) {
                int src = ss[warp][j];
                float wj = ws[warp][j * 4 + head];
                h2x2 hh = *(const h2x2*)&hhb[(size_t)src * 64 + lane * 2];
                float2 f0 = __half22float2(hh.a);
                float2 f1 = __half22float2(hh.b);
                acc.x += wj * f0.x;
                acc.y += wj * f0.y;
                acc.z += wj * f1.x;
                acc.w += wj * f1.y;
            }
            __syncwarp();
        }
        float dh = (head == 0) ? den.x : (head == 1) ? den.y : (head == 2) ? den.z : den.w;
        float inv = 1.f / (dh + 1e-16f);
        o = make_float4(acc.x * inv, acc.y * inv, acc.z * inv, acc.w * inv);
        *(float4*)&out[(size_t)n * 128 + lane * 4] = o;
    }

    *(float4*)&bsum[warp][lane * 4] = o;
    float4 q = make_float4(o.x * o.x, o.y * o.y, o.z * o.z, o.w * o.w);
    *(float4*)&bsq[warp][lane * 4] = q;
    __syncthreads();
    if (threadIdx.x < 128) {
        float s = 0.f, ssq = 0.f;
#pragma unroll
        for (int w2 = 0; w2 < 8; w2++) {
            s += bsum[w2][threadIdx.x];
            ssq += bsq[w2][threadIdx.x];
        }
        atomicAdd(&g_sum[threadIdx.x], s);
        atomicAdd(&g_sq[threadIdx.x], ssq);
    }
}

// ---------------- K4b: finalize per-channel scale/shift ----------------
__global__ void k_bnfinal(const float* __restrict__ gamma, const float* __restrict__ beta) {
    int c = threadIdx.x;
    float inv_n = 1.f / (float)NN;
    float mu = g_sum[c] * inv_n;
    float var = g_sq[c] * inv_n - mu * mu;
    float inv = rsqrtf(var + 1e-5f);
    float sc = gamma[c] * inv;
    g_scale[c] = sc;
    g_shift[c] = beta[c] - mu * sc;
}

// ---------------- K5: normalize + LeakyReLU (in place on d_out) ----------------
__global__ void k_norm(float* __restrict__ out) {
    int tid = blockIdx.x * blockDim.x + threadIdx.x;
    int stride = gridDim.x * blockDim.x;
    float4* o4 = (float4*)out;
    const float4* sc4 = (const float4*)g_scale;
    const float4* sh4 = (const float4*)g_shift;
    for (int j = tid; j < NN * 32; j += stride) {
        float4 v = o4[j];
        float4 sc = __ldg(&sc4[j & 31]);
        float4 sh = __ldg(&sh4[j & 31]);
        v.x = lrelu(v.x * sc.x + sh.x);
        v.y = lrelu(v.y * sc.y + sh.y);
        v.z = lrelu(v.z * sc.z + sh.z);
        v.w = lrelu(v.w * sc.w + sh.w);
        o4[j] = v;
    }
}

// ---------------- launch (single stream, R8 order) ----------------
extern "C" void kernel_launch(void* const* d_in, const int* in_sizes, int n_in,
                              void* d_out, int out_size) {
    const float* x = 0; const void* ei = 0; const float* W = 0;
    const float* att_src = 0; const float* att_dst = 0;
    const float* gamma = 0; const float* beta = 0;
    int n128 = 0;
    for (int i = 0; i < n_in; i++) {
        int sz = in_sizes[i];
        if (sz == NN * 128)        { x = (const float*)d_in[i]; }
        else if (sz == 2 * NE)     { ei = d_in[i]; }
        else if (sz == 128 * 128)  { W = (const float*)d_in[i]; }
        else if (sz == 128) {
            if (n128 == 0)      att_src = (const float*)d_in[i];
            else if (n128 == 1) att_dst = (const float*)d_in[i];
            // n128 == 2 -> bias: cancels exactly under batch-stat BN
            else if (n128 == 3) gamma = (const float*)d_in[i];
            else if (n128 == 4) beta  = (const float*)d_in[i];
            n128++;
        }
    }
    float* out = (float*)d_out;
    if (!x || !ei || !W || !att_src || !att_dst || !gamma || !beta) return;

    k_zero<<<(NN + 255) / 256, 256>>>();
    k_detect<<<1, 32>>>((const unsigned long long*)ei);
    k_convert<<<(NE / 4 + 255) / 256, 256>>>(ei);
    k_psum<<<SCAN_NB, SCAN_NT>>>();
    k_scanp<<<1, 128>>>();
    k_base<<<SCAN_NB, SCAN_NT>>>();
    k_scatter<<<(NE / 4 + 255) / 256, 256>>>(ei);
    k_gemm_att<<<(NN + 127) / 128, 256>>>(x, W, att_src, att_dst);
    k_agg<<<(NN + 7) / 8, 256>>>(out);
    k_bnfinal<<<1, 128>>>(gamma, beta);
    k_norm<<<2048, 256>>>(out);
}

// round 15
// speedup vs baseline: 1.1396x; 1.1396x over previous
#include <cuda_runtime.h>
#include <cuda_fp16.h>

#define NN 100000
#define NE 1600000
#define SCAN_NT 256
#define SCAN_ITEMS 1024
#define SCAN_NB ((NN + SCAN_ITEMS - 1) / SCAN_ITEMS)   // 98

// ---------------- scratch (device globals; no allocation) ----------------
__device__ __align__(16) __half g_hh[(size_t)NN * 128];  // projected features (fp16, gather-only)
__device__ __align__(16) float g_asrc[NN * 4];           // per-node src att logits
__device__ __align__(16) float g_adst[NN * 4];           // per-node dst att logits
__device__ int g_bin[NE];                  // src indices grouped by dst (CSR)
__device__ int g_cnt[NN];
__device__ int g_ofs[NN];
__device__ int g_cur[NN];
__device__ int g_part[SCAN_NB];
__device__ int g_pofs[SCAN_NB];
__device__ int g_is64;
__device__ float g_sum[128];
__device__ float g_sq[128];

__device__ __forceinline__ float lrelu(float v) { return v > 0.f ? v : 0.2f * v; }
__device__ __forceinline__ unsigned f2tf32(float f) {
    unsigned u;
    asm("cvt.rna.tf32.f32 %0, %1;" : "=r"(u) : "f"(f));
    return u;
}
__device__ __forceinline__ void mma_tf32(float c[4], unsigned a0, unsigned a1,
                                         unsigned a2, unsigned a3,
                                         unsigned b0, unsigned b1) {
    asm volatile(
        "mma.sync.aligned.m16n8k8.row.col.f32.tf32.tf32.f32 "
        "{%0,%1,%2,%3}, {%4,%5,%6,%7}, {%8,%9}, {%0,%1,%2,%3};"
        : "+f"(c[0]), "+f"(c[1]), "+f"(c[2]), "+f"(c[3])
        : "r"(a0), "r"(a1), "r"(a2), "r"(a3), "r"(b0), "r"(b1));
}
__device__ __forceinline__ int clampN(long long v) {
    if (v < 0) v = 0;
    if (v > NN - 1) v = NN - 1;
    return (int)v;
}

struct __align__(8) h2x2 { __half2 a, b; };

// ---------------- K-zero ----------------
__global__ void k_zero() {
    int t = blockIdx.x * blockDim.x + threadIdx.x;
    if (t < NN) g_cnt[t] = 0;
    if (t < 128) { g_sum[t] = 0.f; g_sq[t] = 0.f; }
}

// ---------------- K-detect: int64 vs int32 edge_index (parallel ballot) ----------------
__global__ void k_detect(const unsigned long long* __restrict__ e) {
    int lane = threadIdx.x;
    bool good = (e[lane] < (unsigned long long)NN) &&
                (e[32 + lane] < (unsigned long long)NN);
    unsigned b = __ballot_sync(0xffffffffu, good);
    if (lane == 0) g_is64 = (b == 0xffffffffu) ? 1 : 0;
}

// ---------------- K-convert: per-dst histogram, 4 edges/thread vectorized ----------------
__global__ void k_convert(const void* __restrict__ ep) {
    int i4 = blockIdx.x * blockDim.x + threadIdx.x;   // group of 4 edges
    int base = i4 * 4;
    if (base >= NE) return;
    int d[4];
    if (g_is64) {
        const longlong2* e2 = (const longlong2*)((const long long*)ep + NE);
        longlong2 a = e2[i4 * 2];
        longlong2 b = e2[i4 * 2 + 1];
        d[0] = clampN(a.x); d[1] = clampN(a.y); d[2] = clampN(b.x); d[3] = clampN(b.y);
    } else {
        const int4* e4 = (const int4*)((const int*)ep + NE);
        int4 a = e4[i4];
        d[0] = clampN(a.x); d[1] = clampN(a.y); d[2] = clampN(a.z); d[3] = clampN(a.w);
    }
#pragma unroll
    for (int j = 0; j < 4; j++)
        if (base + j < NE) atomicAdd(&g_cnt[d[j]], 1);
}

// ---------------- 3-kernel exclusive scan of g_cnt -> g_ofs (R8 structure) ----------------
__global__ void k_psum() {
    __shared__ int sm[SCAN_NT];
    int b = blockIdx.x, t = threadIdx.x;
    int base = b * SCAN_ITEMS + t * 4;
    int s = 0;
#pragma unroll
    for (int j = 0; j < 4; j++) { int i = base + j; if (i < NN) s += g_cnt[i]; }
    sm[t] = s; __syncthreads();
    for (int off = SCAN_NT / 2; off > 0; off >>= 1) {
        if (t < off) sm[t] += sm[t + off];
        __syncthreads();
    }
    if (t == 0) g_part[b] = sm[0];
}

__global__ void k_scanp() {
    __shared__ int sm[128];
    int t = threadIdx.x;
    int v = (t < SCAN_NB) ? g_part[t] : 0;
    sm[t] = v; __syncthreads();
    for (int off = 1; off < 128; off <<= 1) {
        int a = (t >= off) ? sm[t - off] : 0;
        __syncthreads(); sm[t] += a; __syncthreads();
    }
    if (t < SCAN_NB) g_pofs[t] = sm[t] - v;
}

__global__ void k_base() {
    __shared__ int sm[SCAN_NT];
    int b = blockIdx.x, t = threadIdx.x;
    int base = b * SCAN_ITEMS + t * 4;
    int c[4]; int s = 0;
#pragma unroll
    for (int j = 0; j < 4; j++) {
        int i = base + j;
        c[j] = (i < NN) ? g_cnt[i] : 0;
        s += c[j];
    }
    sm[t] = s; __syncthreads();
    for (int off = 1; off < SCAN_NT; off <<= 1) {
        int a = (t >= off) ? sm[t - off] : 0;
        __syncthreads(); sm[t] += a; __syncthreads();
    }
    int ex = sm[t] - s + g_pofs[b];
#pragma unroll
    for (int j = 0; j < 4; j++) {
        int i = base + j;
        if (i < NN) { g_ofs[i] = ex; g_cur[i] = ex; }
        ex += c[j];
    }
}

// ---------------- K-scatter: CSR fill, 4 edges/thread vectorized ----------------
__global__ void k_scatter(const void* __restrict__ ep) {
    int i4 = blockIdx.x * blockDim.x + threadIdx.x;
    int base = i4 * 4;
    if (base >= NE) return;
    int s[4], d[4];
    if (g_is64) {
        const longlong2* es = (const longlong2*)((const long long*)ep);
        const longlong2* ed = (const longlong2*)((const long long*)ep + NE);
        longlong2 sa = es[i4 * 2], sb = es[i4 * 2 + 1];
        longlong2 da = ed[i4 * 2], db = ed[i4 * 2 + 1];
        s[0] = clampN(sa.x); s[1] = clampN(sa.y); s[2] = clampN(sb.x); s[3] = clampN(sb.y);
        d[0] = clampN(da.x); d[1] = clampN(da.y); d[2] = clampN(db.x); d[3] = clampN(db.y);
    } else {
        const int4* es = (const int4*)((const int*)ep);
        const int4* ed = (const int4*)((const int*)ep + NE);
        int4 sa = es[i4], da = ed[i4];
        s[0] = clampN(sa.x); s[1] = clampN(sa.y); s[2] = clampN(sa.z); s[3] = clampN(sa.w);
        d[0] = clampN(da.x); d[1] = clampN(da.y); d[2] = clampN(da.z); d[3] = clampN(da.w);
    }
#pragma unroll
    for (int j = 0; j < 4; j++) {
        if (base + j < NE) {
            int pos = atomicAdd(&g_cur[d[j]], 1);
            g_bin[pos] = s[j];
        }
    }
}

// ---------------- K1: h = x @ W via tf32 mma.sync + fused att logits ----------------
__global__ __launch_bounds__(256) void k_gemm_att(const float* __restrict__ x,
                                                  const float* __restrict__ W,
                                                  const float* __restrict__ att_src,
                                                  const float* __restrict__ att_dst) {
    __shared__ unsigned xs[128][36];   // x chunk [row][k], tf32
    __shared__ unsigned Wsh[32][136];  // W chunk [k][n], tf32
    __shared__ float attb[256];        // [0:128) att_src, [128:256) att_dst
    int t = threadIdx.x;
    int w = t >> 5, lane = t & 31;
    int r0 = w * 16;
    int row0 = blockIdx.x * 128;
    int lg = lane >> 2, lc = lane & 3;
    attb[t] = (t < 128) ? __ldg(&att_src[t]) : __ldg(&att_dst[t - 128]);

    float c[16][4];
#pragma unroll
    for (int nt = 0; nt < 16; nt++)
#pragma unroll
        for (int j = 0; j < 4; j++) c[nt][j] = 0.f;

    const float4* x4 = (const float4*)x;
    const float4* W4 = (const float4*)W;
    for (int ch = 0; ch < 4; ch++) {
#pragma unroll
        for (int j = 0; j < 4; j++) {           // W chunk [32 k][128 n]
            int f = t + 256 * j;
            int k = f >> 5, c4 = f & 31;
            float4 v = W4[(ch * 32 + k) * 32 + c4];
            uint4 u = make_uint4(f2tf32(v.x), f2tf32(v.y), f2tf32(v.z), f2tf32(v.w));
            *(uint4*)&Wsh[k][c4 * 4] = u;
        }
#pragma unroll
        for (int j = 0; j < 4; j++) {           // x chunk [128 rows][32 k]
            int f = t + 256 * j;
            int row = f >> 3, q = f & 7;
            int gr = row0 + row; if (gr > NN - 1) gr = NN - 1;
            float4 v = x4[(size_t)gr * 32 + ch * 8 + q];
            uint4 u = make_uint4(f2tf32(v.x), f2tf32(v.y), f2tf32(v.z), f2tf32(v.w));
            *(uint4*)&xs[row][q * 4] = u;
        }
        __syncthreads();
#pragma unroll
        for (int ks = 0; ks < 4; ks++) {
            int kc = ks * 8;
            unsigned a0 = xs[r0 + lg][kc + lc];
            unsigned a1 = xs[r0 + lg + 8][kc + lc];
            unsigned a2 = xs[r0 + lg][kc + lc + 4];
            unsigned a3 = xs[r0 + lg + 8][kc + lc + 4];
#pragma unroll
            for (int nt = 0; nt < 16; nt++) {
                unsigned b0 = Wsh[kc + lc][nt * 8 + lg];
                unsigned b1 = Wsh[kc + lc + 4][nt * 8 + lg];
                mma_tf32(c[nt], a0, a1, a2, a3, b0, b1);
            }
        }
        __syncthreads();
    }

    // epilogue: fused attention logits + fp16 h store
    float s1[4] = {0,0,0,0}, s2[4] = {0,0,0,0};
    float d1[4] = {0,0,0,0}, d2[4] = {0,0,0,0};
#pragma unroll
    for (int m = 0; m < 4; m++) {
#pragma unroll
        for (int q = 0; q < 4; q++) {
            int nt = m * 4 + q;
            int col = nt * 8 + 2 * lc;
            float as0 = attb[col], as1 = attb[col + 1];
            float ad0 = attb[128 + col], ad1 = attb[128 + col + 1];
            s1[m] += c[nt][0] * as0 + c[nt][1] * as1;
            d1[m] += c[nt][0] * ad0 + c[nt][1] * ad1;
            s2[m] += c[nt][2] * as0 + c[nt][3] * as1;
            d2[m] += c[nt][2] * ad0 + c[nt][3] * ad1;
        }
    }
#pragma unroll
    for (int off = 1; off <= 2; off <<= 1) {
#pragma unroll
        for (int m = 0; m < 4; m++) {
            s1[m] += __shfl_xor_sync(0xffffffffu, s1[m], off);
            s2[m] += __shfl_xor_sync(0xffffffffu, s2[m], off);
            d1[m] += __shfl_xor_sync(0xffffffffu, d1[m], off);
            d2[m] += __shfl_xor_sync(0xffffffffu, d2[m], off);
        }
    }
    int rowA = row0 + r0 + lg;
    int rowB = rowA + 8;
    if (lc == 0) {
        if (rowA < NN) {
            *(float4*)&g_asrc[rowA * 4] = make_float4(s1[0], s1[1], s1[2], s1[3]);
            *(float4*)&g_adst[rowA * 4] = make_float4(d1[0], d1[1], d1[2], d1[3]);
        }
        if (rowB < NN) {
            *(float4*)&g_asrc[rowB * 4] = make_float4(s2[0], s2[1], s2[2], s2[3]);
            *(float4*)&g_adst[rowB * 4] = make_float4(d2[0], d2[1], d2[2], d2[3]);
        }
    }
    __half2* hh2 = (__half2*)g_hh;
    if (rowA < NN) {
#pragma unroll
        for (int nt = 0; nt < 16; nt++)
            hh2[(size_t)rowA * 64 + nt * 4 + lc] =
                __float22half2_rn(make_float2(c[nt][0], c[nt][1]));
    }
    if (rowB < NN) {
#pragma unroll
        for (int nt = 0; nt < 16; nt++)
            hh2[(size_t)rowB * 64 + nt * 4 + lc] =
                __float22half2_rn(make_float2(c[nt][2], c[nt][3]));
    }
}

// ---------------- K3: warp-per-node GAT aggregation (R8 form, FROZEN) ----------------
__global__ __launch_bounds__(256) void k_agg(float* __restrict__ out) {
    __shared__ int   ss[8][32];
    __shared__ float ws[8][32 * 4];
    __shared__ float bsum[8][128];
    __shared__ float bsq[8][128];
    int warp = threadIdx.x >> 5, lane = threadIdx.x & 31;
    int n = blockIdx.x * 8 + warp;
    int head = lane >> 3;
    float4 o = make_float4(0.f, 0.f, 0.f, 0.f);

    if (n < NN) {
        int beg = g_ofs[n], cnt = g_cnt[n];
        float4 ad = *(const float4*)&g_adst[n * 4];
        float4 acc = make_float4(0.f, 0.f, 0.f, 0.f);
        float4 den = make_float4(0.f, 0.f, 0.f, 0.f);

        for (int c0 = 0; c0 < cnt; c0 += 32) {
            int m = cnt - c0; if (m > 32) m = 32;
            float4 w = make_float4(0.f, 0.f, 0.f, 0.f);
            int s = 0;
            if (lane < m) {
                s = g_bin[beg + c0 + lane];
                float4 a = *(const float4*)&g_asrc[s * 4];
                w.x = __expf(lrelu(a.x + ad.x));
                w.y = __expf(lrelu(a.y + ad.y));
                w.z = __expf(lrelu(a.z + ad.z));
                w.w = __expf(lrelu(a.w + ad.w));
            }
            ss[warp][lane] = s;
            *(float4*)&ws[warp][lane * 4] = w;
            float4 wr = w;
            for (int off = 16; off > 0; off >>= 1) {
                wr.x += __shfl_xor_sync(0xffffffffu, wr.x, off);
                wr.y += __shfl_xor_sync(0xffffffffu, wr.y, off);
                wr.z += __shfl_xor_sync(0xffffffffu, wr.z, off);
                wr.w += __shfl_xor_sync(0xffffffffu, wr.w, off);
            }
            den.x += wr.x; den.y += wr.y; den.z += wr.z; den.w += wr.w;
            __syncwarp();
            for (int j = 0; j < m; j++) {
                int src = ss[warp][j];
                float wj = ws[warp][j * 4 + head];
                const __half2* hrow = (const __half2*)&g_hh[(size_t)src * 128];
                h2x2 hh = *(const h2x2*)&hrow[lane * 2];
                float2 f0 = __half22float2(hh.a);
                float2 f1 = __half22float2(hh.b);
                acc.x += wj * f0.x;
                acc.y += wj * f0.y;
                acc.z += wj * f1.x;
                acc.w += wj * f1.y;
            }
            __syncwarp();
        }
        float dh = (head == 0) ? den.x : (head == 1) ? den.y : (head == 2) ? den.z : den.w;
        float inv = 1.f / (dh + 1e-16f);
        o = make_float4(acc.x * inv, acc.y * inv, acc.z * inv, acc.w * inv);
        *(float4*)&out[(size_t)n * 128 + lane * 4] = o;
    }

    *(float4*)&bsum[warp][lane * 4] = o;
    float4 q = make_float4(o.x * o.x, o.y * o.y, o.z * o.z, o.w * o.w);
    *(float4*)&bsq[warp][lane * 4] = q;
    __syncthreads();
    if (threadIdx.x < 128) {
        float s = 0.f, ssq = 0.f;
#pragma unroll
        for (int w2 = 0; w2 < 8; w2++) {
            s += bsum[w2][threadIdx.x];
            ssq += bsq[w2][threadIdx.x];
        }
        atomicAdd(&g_sum[threadIdx.x], s);
        atomicAdd(&g_sq[threadIdx.x], ssq);
    }
}

// ---------------- K5: BN finalize + normalize + LeakyReLU (fused, in place) ----------------
__global__ void k_norm(float* __restrict__ out,
                       const float* __restrict__ gamma, const float* __restrict__ beta) {
    __shared__ float sscale[128];
    __shared__ float sshift[128];
    int t = threadIdx.x;
    if (t < 128) {
        float inv_n = 1.f / (float)NN;
        float mu = g_sum[t] * inv_n;
        float var = g_sq[t] * inv_n - mu * mu;
        float inv = rsqrtf(var + 1e-5f);
        float sc = __ldg(&gamma[t]) * inv;
        sscale[t] = sc;
        sshift[t] = __ldg(&beta[t]) - mu * sc;
    }
    __syncthreads();
    int tid = blockIdx.x * blockDim.x + t;
    int stride = gridDim.x * blockDim.x;
    float4* o4 = (float4*)out;
    const float4* sc4 = (const float4*)sscale;
    const float4* sh4 = (const float4*)sshift;
    for (int j = tid; j < NN * 32; j += stride) {
        float4 v = o4[j];
        float4 sc = sc4[j & 31];
        float4 sh = sh4[j & 31];
        v.x = lrelu(v.x * sc.x + sh.x);
        v.y = lrelu(v.y * sc.y + sh.y);
        v.z = lrelu(v.z * sc.z + sh.z);
        v.w = lrelu(v.w * sc.w + sh.w);
        o4[j] = v;
    }
}

// ---------------- launch: fork-join (gemm on side stream || binning on main) ----------------
extern "C" void kernel_launch(void* const* d_in, const int* in_sizes, int n_in,
                              void* d_out, int out_size) {
    const float* x = 0; const void* ei = 0; const float* W = 0;
    const float* att_src = 0; const float* att_dst = 0;
    const float* gamma = 0; const float* beta = 0;
    int n128 = 0;
    for (int i = 0; i < n_in; i++) {
        int sz = in_sizes[i];
        if (sz == NN * 128)        { x = (const float*)d_in[i]; }
        else if (sz == 2 * NE)     { ei = d_in[i]; }
        else if (sz == 128 * 128)  { W = (const float*)d_in[i]; }
        else if (sz == 128) {
            if (n128 == 0)      att_src = (const float*)d_in[i];
            else if (n128 == 1) att_dst = (const float*)d_in[i];
            // n128 == 2 -> bias: cancels exactly under batch-stat BN
            else if (n128 == 3) gamma = (const float*)d_in[i];
            else if (n128 == 4) beta  = (const float*)d_in[i];
            n128++;
        }
    }
    float* out = (float*)d_out;
    if (!x || !ei || !W || !att_src || !att_dst || !gamma || !beta) return;

    // one-time stream/event creation (host objects only; no device memory)
    static cudaStream_t s2 = 0;
    static cudaEvent_t ev0 = 0, ev1 = 0;
    if (!s2) {
        cudaStreamCreateWithFlags(&s2, cudaStreamNonBlocking);
        cudaEventCreateWithFlags(&ev0, cudaEventDisableTiming);
        cudaEventCreateWithFlags(&ev1, cudaEventDisableTiming);
    }

    // fork: GEMM+att (DRAM/tensor-bound) runs concurrent with binning (atomic-bound)
    cudaEventRecord(ev0, 0);
    cudaStreamWaitEvent(s2, ev0, 0);
    k_gemm_att<<<(NN + 127) / 128, 256, 0, s2>>>(x, W, att_src, att_dst);
    cudaEventRecord(ev1, s2);

    k_zero<<<(NN + 255) / 256, 256>>>();
    k_detect<<<1, 32>>>((const unsigned long long*)ei);
    k_convert<<<(NE / 4 + 255) / 256, 256>>>(ei);
    k_psum<<<SCAN_NB, SCAN_NT>>>();
    k_scanp<<<1, 128>>>();
    k_base<<<SCAN_NB, SCAN_NT>>>();
    k_scatter<<<(NE / 4 + 255) / 256, 256>>>(ei);

    // join: aggregation needs both h/logits and CSR
    cudaStreamWaitEvent(0, ev1, 0);
    k_agg<<<(NN + 7) / 8, 256>>>(out);
    k_norm<<<2048, 256>>>(out, gamma, beta);
}